// round 4
// baseline (speedup 1.0000x reference)
#include <cuda_runtime.h>

// Problem constants: LX=8, LY=4, D=4, PHYS=2, batch=128
#define NB   128
#define NCOL 16384

// Scratch (device global: no allocation allowed)
__device__ __align__(16) float g_C[NB * NCOL];

// f32x2 packed helpers (sm_100+ PTX)
#define FMA2(d, a, b) asm("fma.rn.f32x2 %0, %1, %2, %0;" : "+l"(d) : "l"(a), "l"(b))
#define PACK2(d, lo, hi) asm("mov.b64 %0, {%1, %2};" : "=l"(d) : "f"(lo), "f"(hi))
#define UNPACK2(lo, hi, s) asm("mov.b64 {%0, %1}, %2;" : "=f"(lo), "=f"(hi) : "l"(s))

// ---------------------------------------------------------------------------
// Kernel 1 (fused hidden + gemm):
//   H[b,k] = relu(b1[k] + cfg[b,:]·W1[:,k])           (computed per block)
//   C[b,n] = 0.001 * (b2[n] + H[b,:]·W2[:,n])
// grid (32, 4): block covers 512 columns x 32 batches; 128 blocks = 1 wave.
// Batch pairs packed into f32x2 accumulators -> FFMA2 at 128 FMA/cyc/SM.
// ---------------------------------------------------------------------------
__global__ void __launch_bounds__(512, 1)
k_gemm(const int* __restrict__ cfg,
       const float* __restrict__ W1,
       const float* __restrict__ b1,
       const float* __restrict__ W2,
       const float* __restrict__ b2) {
    __shared__ __align__(16) float Hs[64 * 32];   // [k][b_local], pairs adjacent
    __shared__ int cs[32 * 32];                    // [b_local][k]

    const int tid = threadIdx.x;
    const int n   = blockIdx.x * 512 + tid;
    const int b0  = blockIdx.y * 32;

    // stage cfg for this block's 32 batches
    for (int idx = tid; idx < 32 * 32; idx += 512)
        cs[idx] = cfg[b0 * 32 + idx];
    __syncthreads();

    // hidden layer: thread owns hidden index j = tid & 63, 4 batches
    {
        const int j = tid & 63;
        float w1c[32];
#pragma unroll
        for (int k = 0; k < 32; k++) w1c[k] = W1[k * 64 + j];
        const float bj = b1[j];
#pragma unroll
        for (int m = 0; m < 4; m++) {
            const int bl = (tid >> 6) + 8 * m;
            float acc = bj;
#pragma unroll
            for (int k = 0; k < 32; k++)
                acc = fmaf((float)cs[bl * 32 + k], w1c[k], acc);
            Hs[j * 32 + bl] = fmaxf(acc, 0.0f);
        }
    }
    __syncthreads();

    // main GEMM: 16 f32x2 accumulators = 32 batches
    unsigned long long acc[16];
    {
        const float bias = b2[n];
        unsigned long long bias2;
        PACK2(bias2, bias, bias);
#pragma unroll
        for (int q = 0; q < 16; q++) acc[q] = bias2;
    }

#pragma unroll 4
    for (int k = 0; k < 64; k++) {
        const float w = W2[k * NCOL + n];
        unsigned long long w2p;
        PACK2(w2p, w, w);
        const ulonglong2* hp = (const ulonglong2*)(Hs + k * 32);
#pragma unroll
        for (int q = 0; q < 8; q++) {
            ulonglong2 h = hp[q];
            FMA2(acc[2 * q],     h.x, w2p);
            FMA2(acc[2 * q + 1], h.y, w2p);
        }
    }

#pragma unroll
    for (int q = 0; q < 16; q++) {
        float lo, hi;
        UNPACK2(lo, hi, acc[q]);
        g_C[(b0 + 2 * q)     * NCOL + n] = 0.001f * lo;
        g_C[(b0 + 2 * q + 1) * NCOL + n] = 0.001f * hi;
    }
}

// ---------------------------------------------------------------------------
// Kernel 2: per-batch tensor assembly + transfer-matrix chain.
// One block (256 threads) per batch.
//
// bot_u[i,j], top_u[I,J] stored TRANSPOSED with stride 20:
//   botT[u][j*20 + i], topT[u][J*20 + I]  -> column reads become LDS.128.
// V stored transposed stride 17: VT[col*17 + row] -> conflict-free column read.
// P4[u][j*16 + I] row-major -> LDS.128 row reads.
//
// Chain: P_u[j,I] = sum_i bot_u[i,j] V[i,I];  V'[j,J] = sum_{u,I} P_u[j,I] top_u[I,J]
// ---------------------------------------------------------------------------
__global__ void __launch_bounds__(256, 1)
k_chain(const int* __restrict__ cfg,
        const float* __restrict__ A,
        float* __restrict__ out) {
    __shared__ float s0[256], s1[256], s2[256], s3[256];
    __shared__ __align__(16) float botT[4][320];
    __shared__ __align__(16) float topT[4][320];
    __shared__ __align__(16) float P4[4][256];
    __shared__ float VT[288];
    __shared__ int   c[32];

    const int b = blockIdx.x;
    const int t = threadIdx.x;

    if (t < 32) c[t] = cfg[b * 32 + t];
    VT[t] = 0.0f;
    if (t < 32) VT[256 + t] = 0.0f;
    __syncthreads();
    if (t == 0) VT[0] = 1.0f;   // V[0,0] = 1 (VT[0*17+0])

    const float* Crow = g_C + b * NCOL;

    const int i = t >> 4, j = t & 15;
    const int l = i >> 2, L = i & 3, r = j >> 2, R = j & 3;
    const int j2 = t >> 4, I = t & 15;   // roles in chain phases (J == I slot)

    float accOut = 0.0f;

    for (int x = 0; x < 8; x++) {
        // ---- stage selected A slices ----
        const float* Ax = A + x * 2048;
        s0[t] = Ax[         t * 2 + c[x * 4 + 0]];
        s1[t] = Ax[ 512   + t * 2 + c[x * 4 + 1]];
        s2[t] = Ax[1024   + t * 2 + c[x * 4 + 2]];
        s3[t] = Ax[1536   + t * 2 + c[x * 4 + 3]];
        __syncthreads();   // also orders prev-iter VT writes before P reads

        // ---- build bot/top (+ NN correction), stored transposed ----
        float4 cb = *(const float4*)(Crow + x * 1024 + t * 4);
        float4 ct = *(const float4*)(Crow + 8192 + x * 1024 + t * 4);

        float r0v[4], r3v[4];
#pragma unroll
        for (int u = 0; u < 4; u++) {
            r0v[u] = s0[l * 64 + r * 16 + u];       // s0[l,r,0,u]
            r3v[u] = s3[L * 64 + R * 16 + u * 4];   // s3[L,R,u,0]
        }
#pragma unroll
        for (int U = 0; U < 4; U++) {
            float a0 = 0.0f;
#pragma unroll
            for (int u = 0; u < 4; u++)
                a0 = fmaf(r0v[u], s1[L * 64 + R * 16 + u * 4 + U], a0);
            botT[U][j * 20 + i] = a0 + ((const float*)&cb)[U];
        }
#pragma unroll
        for (int d = 0; d < 4; d++) {
            float a0 = 0.0f;
#pragma unroll
            for (int u = 0; u < 4; u++)
                a0 = fmaf(s2[l * 64 + r * 16 + d * 4 + u], r3v[u], a0);
            topT[d][j * 20 + i] = a0 + ((const float*)&ct)[d];
        }
        __syncthreads();

        // ---- P phase: P_u[j2, I] = sum_ii bot_u[ii, j2] * V[ii, I] ----
        float vl[16];
#pragma unroll
        for (int ii = 0; ii < 16; ii++) vl[ii] = VT[I * 17 + ii];
#pragma unroll
        for (int u = 0; u < 4; u++) {
            const float4* bp = (const float4*)&botT[u][j2 * 20];
            float p = 0.0f;
#pragma unroll
            for (int q = 0; q < 4; q++) {
                float4 b4 = bp[q];
                p = fmaf(b4.x, vl[4 * q + 0], p);
                p = fmaf(b4.y, vl[4 * q + 1], p);
                p = fmaf(b4.z, vl[4 * q + 2], p);
                p = fmaf(b4.w, vl[4 * q + 3], p);
            }
            P4[u][j2 * 16 + I] = p;
        }
        __syncthreads();

        // ---- V' phase: V'[j2, J] = sum_u sum_I2 P_u[j2, I2] * top_u[I2, J] ----
        float acc = 0.0f;
#pragma unroll
        for (int u = 0; u < 4; u++) {
            const float4* pp = (const float4*)&P4[u][j2 * 16];
            const float4* tp = (const float4*)&topT[u][I * 20];   // J == I
#pragma unroll
            for (int q = 0; q < 4; q++) {
                float4 p4 = pp[q];
                float4 t4 = tp[q];
                acc = fmaf(p4.x, t4.x, acc);
                acc = fmaf(p4.y, t4.y, acc);
                acc = fmaf(p4.z, t4.z, acc);
                acc = fmaf(p4.w, t4.w, acc);
            }
        }
        __syncthreads();                // all P4/topT reads done before overwrite
        VT[I * 17 + j2] = acc;          // VT[col=J][row=j]  (next iter synced by staging barrier)
        accOut = acc;
    }

    if (t == 0) out[b] = accOut;        // thread 0 owns (j=0, J=0)
}

// ---------------------------------------------------------------------------
extern "C" void kernel_launch(void* const* d_in, const int* in_sizes, int n_in,
                              void* d_out, int out_size) {
    const int*   cfg = (const int*)d_in[0];
    const float* A   = (const float*)d_in[1];
    const float* W1  = (const float*)d_in[2];
    const float* b1  = (const float*)d_in[3];
    const float* W2  = (const float*)d_in[4];
    const float* b2  = (const float*)d_in[5];
    float* out = (float*)d_out;

    k_gemm<<<dim3(32, 4), 512>>>(cfg, W1, b1, W2, b2);
    k_chain<<<NB, 256>>>(cfg, A, out);
}

// round 5
// speedup vs baseline: 1.2281x; 1.2281x over previous
#include <cuda_runtime.h>

// Problem constants: LX=8, LY=4, D=4, PHYS=2, batch=128
#define NB   128
#define NCOL 16384

// Scratch (device global: no allocation allowed)
__device__ __align__(16) float g_C[NB * NCOL];

// f32x2 packed helpers (sm_100+ PTX)
#define FMA2(d, a, b) asm("fma.rn.f32x2 %0, %1, %2, %0;" : "+l"(d) : "l"(a), "l"(b))
#define PACK2(d, lo, hi) asm("mov.b64 %0, {%1, %2};" : "=l"(d) : "f"(lo), "f"(hi))
#define UNPACK2(lo, hi, s) asm("mov.b64 {%0, %1}, %2;" : "=f"(lo), "=f"(hi) : "l"(s))

// ---------------------------------------------------------------------------
// Kernel 1 (fused hidden + gemm):
//   H[b,k] = relu(b1[k] + cfg[b,:]·W1[:,k])
//   C[b,n] = 0.001 * (b2[n] + H[b,:]·W2[:,n])
// grid (32, 4): 128 blocks = 1 wave; 32 batches/block packed in f32x2 accs.
// ---------------------------------------------------------------------------
__global__ void __launch_bounds__(512, 1)
k_gemm(const int* __restrict__ cfg,
       const float* __restrict__ W1,
       const float* __restrict__ b1,
       const float* __restrict__ W2,
       const float* __restrict__ b2) {
    __shared__ __align__(16) float Hs[64 * 32];
    __shared__ int cs[32 * 32];

    const int tid = threadIdx.x;
    const int n   = blockIdx.x * 512 + tid;
    const int b0  = blockIdx.y * 32;

    for (int idx = tid; idx < 32 * 32; idx += 512)
        cs[idx] = cfg[b0 * 32 + idx];
    __syncthreads();

    {
        const int j = tid & 63;
        float w1c[32];
#pragma unroll
        for (int k = 0; k < 32; k++) w1c[k] = W1[k * 64 + j];
        const float bj = b1[j];
#pragma unroll
        for (int m = 0; m < 4; m++) {
            const int bl = (tid >> 6) + 8 * m;
            float acc = bj;
#pragma unroll
            for (int k = 0; k < 32; k++)
                acc = fmaf((float)cs[bl * 32 + k], w1c[k], acc);
            Hs[j * 32 + bl] = fmaxf(acc, 0.0f);
        }
    }
    __syncthreads();

    unsigned long long acc[16];
    {
        const float bias = b2[n];
        unsigned long long bias2;
        PACK2(bias2, bias, bias);
#pragma unroll
        for (int q = 0; q < 16; q++) acc[q] = bias2;
    }

#pragma unroll 8
    for (int k = 0; k < 64; k++) {
        const float w = W2[k * NCOL + n];
        unsigned long long w2p;
        PACK2(w2p, w, w);
        const ulonglong2* hp = (const ulonglong2*)(Hs + k * 32);
#pragma unroll
        for (int q = 0; q < 8; q++) {
            ulonglong2 h = hp[q];
            FMA2(acc[2 * q],     h.x, w2p);
            FMA2(acc[2 * q + 1], h.y, w2p);
        }
    }

#pragma unroll
    for (int q = 0; q < 16; q++) {
        float lo, hi;
        UNPACK2(lo, hi, acc[q]);
        g_C[(b0 + 2 * q)     * NCOL + n] = 0.001f * lo;
        g_C[(b0 + 2 * q + 1) * NCOL + n] = 0.001f * hi;
    }
}

// ---------------------------------------------------------------------------
// Kernel 2: per-batch tensor assembly + transfer-matrix chain.
//
// Phase 1 (parallel over all 8 x): gather A slices (double-buffered staging,
// software prefetch of next x's LDGs), build botT/topT for ALL x into smem:
//   botT[x][u][j*20 + i], topT[x][d][J*20 + I]   (stride 20: float4-aligned,
//   2-way-max write conflicts, broadcast reads in phase 2)
//
// Phase 2 (sequential chain, smem-only, 2 barriers/iter):
//   P_u[j,I] = sum_i bot_u[i,j] V[i,I]
//   V'[j,J]  = sum_{u,I} P_u[j,I] top_u[I,J]
//   V double-buffered, stride-20 transposed: VT[col*20 + row].
// ---------------------------------------------------------------------------
#define SM_S    0            // [2][4][256] = 2048
#define SM_BOT  2048         // [8][4][320] = 10240
#define SM_TOP  12288        // 10240
#define SM_P4   22528        // [4][256] = 1024
#define SM_VT   23552        // [2][320] = 640
#define SM_CFG  24192        // 32 ints
#define SMEM_CH ((24192 + 32) * 4)

__global__ void __launch_bounds__(256, 1)
k_chain(const int* __restrict__ cfg,
        const float* __restrict__ A,
        float* __restrict__ out) {
    extern __shared__ __align__(16) float sm[];
    float* botT = sm + SM_BOT;
    float* topT = sm + SM_TOP;
    float* P4   = sm + SM_P4;
    float* VT   = sm + SM_VT;
    int*   c    = (int*)(sm + SM_CFG);

    const int b = blockIdx.x;
    const int t = threadIdx.x;

    if (t < 32) c[t] = cfg[b * 32 + t];
    __syncthreads();

    const float* Crow = g_C + b * NCOL;
    const int i = t >> 4, j = t & 15;
    const int l = i >> 2, L = i & 3, r = j >> 2, R = j & 3;

    // ---------------- Phase 1: build botT/topT for all x ----------------
    float rA0, rA1, rA2, rA3;
    float4 cb, ct;
    {
        rA0 = A[         t * 2 + c[0]];
        rA1 = A[ 512   + t * 2 + c[1]];
        rA2 = A[1024   + t * 2 + c[2]];
        rA3 = A[1536   + t * 2 + c[3]];
        cb  = *(const float4*)(Crow + t * 4);
        ct  = *(const float4*)(Crow + 8192 + t * 4);
    }

    for (int x = 0; x < 8; x++) {
        float* sb = sm + SM_S + (x & 1) * 1024;
        sb[t]       = rA0;
        sb[256 + t] = rA1;
        sb[512 + t] = rA2;
        sb[768 + t] = rA3;
        __syncthreads();

        // prefetch next x (overlaps with compute below)
        float nA0, nA1, nA2, nA3;
        float4 ncb, nct;
        if (x < 7) {
            const float* Ax = A + (x + 1) * 2048;
            nA0 = Ax[         t * 2 + c[(x + 1) * 4 + 0]];
            nA1 = Ax[ 512   + t * 2 + c[(x + 1) * 4 + 1]];
            nA2 = Ax[1024   + t * 2 + c[(x + 1) * 4 + 2]];
            nA3 = Ax[1536   + t * 2 + c[(x + 1) * 4 + 3]];
            ncb = *(const float4*)(Crow + (x + 1) * 1024 + t * 4);
            nct = *(const float4*)(Crow + 8192 + (x + 1) * 1024 + t * 4);
        }

        // build bot/top for this x
        float r0v[4], r3v[4];
#pragma unroll
        for (int u = 0; u < 4; u++) {
            r0v[u] = sb[l * 64 + r * 16 + u];                 // s0[l,r,0,u]
            r3v[u] = sb[768 + L * 64 + R * 16 + u * 4];       // s3[L,R,u,0]
        }
        float* bx = botT + x * 1280;
        float* tx = topT + x * 1280;
#pragma unroll
        for (int U = 0; U < 4; U++) {
            float a0 = 0.0f;
#pragma unroll
            for (int u = 0; u < 4; u++)
                a0 = fmaf(r0v[u], sb[256 + L * 64 + R * 16 + u * 4 + U], a0);
            bx[U * 320 + j * 20 + i] = a0 + ((const float*)&cb)[U];
        }
#pragma unroll
        for (int d = 0; d < 4; d++) {
            float a0 = 0.0f;
#pragma unroll
            for (int u = 0; u < 4; u++)
                a0 = fmaf(sb[512 + l * 64 + r * 16 + d * 4 + u], r3v[u], a0);
            tx[d * 320 + j * 20 + i] = a0 + ((const float*)&ct)[d];
        }

        rA0 = nA0; rA1 = nA1; rA2 = nA2; rA3 = nA3;
        cb = ncb; ct = nct;
    }

    // init V (buffer 0): V[0,0] = 1
    for (int idx = t; idx < 640; idx += 256)
        VT[idx] = (idx == 0) ? 1.0f : 0.0f;
    __syncthreads();   // botT/topT + VT visible

    // ---------------- Phase 2: transfer-matrix chain ----------------
    const int j2 = t >> 4, I = t & 15;   // this thread owns (j=j2, J=I)
    float accOut = 0.0f;

    for (int x = 0; x < 8; x++) {
        const float* Vin  = VT + (x & 1) * 320;
        float*       Vout = VT + ((x + 1) & 1) * 320;
        const float* bx = botT + x * 1280;
        const float* tx = topT + x * 1280;

        // P_u[j2, I] = sum_ii bot_u[ii, j2] * V[ii, I]
        float vl[16];
#pragma unroll
        for (int q = 0; q < 4; q++) {
            float4 v4 = *(const float4*)(Vin + I * 20 + q * 4);
            vl[4 * q + 0] = v4.x; vl[4 * q + 1] = v4.y;
            vl[4 * q + 2] = v4.z; vl[4 * q + 3] = v4.w;
        }
#pragma unroll
        for (int u = 0; u < 4; u++) {
            const float4* bp = (const float4*)(bx + u * 320 + j2 * 20);
            float p = 0.0f;
#pragma unroll
            for (int q = 0; q < 4; q++) {
                float4 b4 = bp[q];
                p = fmaf(b4.x, vl[4 * q + 0], p);
                p = fmaf(b4.y, vl[4 * q + 1], p);
                p = fmaf(b4.z, vl[4 * q + 2], p);
                p = fmaf(b4.w, vl[4 * q + 3], p);
            }
            P4[u * 256 + j2 * 16 + I] = p;
        }
        __syncthreads();

        // V'[j2, J=I] = sum_u sum_I2 P_u[j2, I2] * top_u[I2, J]
        float acc = 0.0f;
#pragma unroll
        for (int u = 0; u < 4; u++) {
            const float4* pp = (const float4*)(P4 + u * 256 + j2 * 16);
            const float4* tp = (const float4*)(tx + u * 320 + I * 20);
#pragma unroll
            for (int q = 0; q < 4; q++) {
                float4 p4 = pp[q];
                float4 t4 = tp[q];
                acc = fmaf(p4.x, t4.x, acc);
                acc = fmaf(p4.y, t4.y, acc);
                acc = fmaf(p4.z, t4.z, acc);
                acc = fmaf(p4.w, t4.w, acc);
            }
        }
        Vout[I * 20 + j2] = acc;     // VT[col=J][row=j]
        accOut = acc;
        __syncthreads();             // P4 reads done + Vout visible
    }

    if (t == 0) out[b] = accOut;     // thread 0 owns (j=0, J=0)
}

// ---------------------------------------------------------------------------
extern "C" void kernel_launch(void* const* d_in, const int* in_sizes, int n_in,
                              void* d_out, int out_size) {
    const int*   cfg = (const int*)d_in[0];
    const float* A   = (const float*)d_in[1];
    const float* W1  = (const float*)d_in[2];
    const float* b1  = (const float*)d_in[3];
    const float* W2  = (const float*)d_in[4];
    const float* b2  = (const float*)d_in[5];
    float* out = (float*)d_out;

    cudaFuncSetAttribute(k_chain, cudaFuncAttributeMaxDynamicSharedMemorySize,
                         SMEM_CH);

    k_gemm<<<dim3(32, 4), 512>>>(cfg, W1, b1, W2, b2);
    k_chain<<<NB, 256, SMEM_CH>>>(cfg, A, out);
}

// round 6
// speedup vs baseline: 1.3099x; 1.0667x over previous
#include <cuda_runtime.h>

// Problem constants: LX=8, LY=4, D=4, PHYS=2, batch=128
#define NB   128
#define NCOL 16384

__device__ __align__(16) float g_C[NB * NCOL];

// f32x2 packed helpers (sm_100+ PTX)
#define FMA2(d, a, b) asm("fma.rn.f32x2 %0, %1, %2, %0;" : "+l"(d) : "l"(a), "l"(b))
#define PACK2(d, lo, hi) asm("mov.b64 %0, {%1, %2};" : "=l"(d) : "f"(lo), "f"(hi))
#define UNPACK2(lo, hi, s) asm("mov.b64 {%0, %1}, %2;" : "=f"(lo), "=f"(hi) : "l"(s))

// ---------------------------------------------------------------------------
// Kernel 1 (fused hidden + gemm):
//   H[b,k] = relu(b1[k] + cfg[b,:]·W1[:,k])
//   C[b,n] = 0.001 * (b2[n] + H[b,:]·W2[:,n])
// ---------------------------------------------------------------------------
__global__ void __launch_bounds__(512, 1)
k_gemm(const int* __restrict__ cfg,
       const float* __restrict__ W1,
       const float* __restrict__ b1,
       const float* __restrict__ W2,
       const float* __restrict__ b2) {
    __shared__ __align__(16) float Hs[64 * 32];
    __shared__ int cs[32 * 32];

    const int tid = threadIdx.x;
    const int n   = blockIdx.x * 512 + tid;
    const int b0  = blockIdx.y * 32;

    for (int idx = tid; idx < 32 * 32; idx += 512)
        cs[idx] = cfg[b0 * 32 + idx];
    __syncthreads();

    {
        const int j = tid & 63;
        float w1c[32];
#pragma unroll
        for (int k = 0; k < 32; k++) w1c[k] = W1[k * 64 + j];
        const float bj = b1[j];
#pragma unroll
        for (int m = 0; m < 4; m++) {
            const int bl = (tid >> 6) + 8 * m;
            float acc = bj;
#pragma unroll
            for (int k = 0; k < 32; k++)
                acc = fmaf((float)cs[bl * 32 + k], w1c[k], acc);
            Hs[j * 32 + bl] = fmaxf(acc, 0.0f);
        }
    }
    __syncthreads();

    unsigned long long acc[16];
    {
        const float bias = b2[n];
        unsigned long long bias2;
        PACK2(bias2, bias, bias);
#pragma unroll
        for (int q = 0; q < 16; q++) acc[q] = bias2;
    }

#pragma unroll 8
    for (int k = 0; k < 64; k++) {
        const float w = W2[k * NCOL + n];
        unsigned long long w2p;
        PACK2(w2p, w, w);
        const ulonglong2* hp = (const ulonglong2*)(Hs + k * 32);
#pragma unroll
        for (int q = 0; q < 8; q++) {
            ulonglong2 h = hp[q];
            FMA2(acc[2 * q],     h.x, w2p);
            FMA2(acc[2 * q + 1], h.y, w2p);
        }
    }

#pragma unroll
    for (int q = 0; q < 16; q++) {
        float lo, hi;
        UNPACK2(lo, hi, acc[q]);
        g_C[(b0 + 2 * q)     * NCOL + n] = 0.001f * lo;
        g_C[(b0 + 2 * q + 1) * NCOL + n] = 0.001f * hi;
    }
}

// ---------------------------------------------------------------------------
// Kernel 2: per-batch assembly + SPLIT transfer-matrix chain.
//
// Phase 1: single-barrier staging of all 8 x-sites' A gathers (MLP=32), then
// barrier-free builds writing both layouts (stride 20 everywhere):
//   botT[x][u][j*20+i]=bot_u[i,j]   botN[x][u][i*20+j]=bot_u[i,j]  (top same)
//
// Phase 2: half 0 (threads 0-127): V' = sum_u bot_u^T V top_u, x=0..3
//          half 1 (threads 128-255): A' = sum_u bot_u A top_u^T, x=7..4
//            (identical code with botN/topN pointers)
//          each half-thread owns 2 elements (j2, j2+8) x I; named barriers.
// Final: answer = elementwise dot of the two 256-element results.
// ---------------------------------------------------------------------------
#define STR   20
#define PLANE 320      // 16*STR
#define XPL   1280     // 4*PLANE

#define SM_S    0       // 8192
#define SM_BOTT 8192    // 10240
#define SM_TOPT 18432   // 10240
#define SM_BOTN 28672   // 10240
#define SM_TOPN 38912   // 10240
#define SM_P4   49152   // 2*1024
#define SM_V    51200   // 2*640
#define SM_VF   52480   // 512
#define SM_RED  52992   // 16
#define SM_CFG  53008   // 32 ints
#define SMEM_CH (53040 * 4)

__global__ void __launch_bounds__(256, 1)
k_chain(const int* __restrict__ cfg,
        const float* __restrict__ A,
        float* __restrict__ out) {
    extern __shared__ __align__(16) float sm[];
    int* c = (int*)(sm + SM_CFG);

    const int b = blockIdx.x;
    const int t = threadIdx.x;

    if (t < 32) c[t] = cfg[b * 32 + t];
    __syncthreads();

    const float* Crow = g_C + b * NCOL;

    // ---------------- Phase 1: stage all s, build all bot/top ----------------
    {
        float g[32];
#pragma unroll
        for (int x = 0; x < 8; x++) {
            const float* Ax = A + x * 2048 + t * 2;
            g[x * 4 + 0] = Ax[          c[x * 4 + 0]];
            g[x * 4 + 1] = Ax[ 512    + c[x * 4 + 1]];
            g[x * 4 + 2] = Ax[ 1024   + c[x * 4 + 2]];
            g[x * 4 + 3] = Ax[ 1536   + c[x * 4 + 3]];
        }
#pragma unroll
        for (int x = 0; x < 8; x++) {
#pragma unroll
            for (int y = 0; y < 4; y++)
                sm[SM_S + x * 1024 + y * 256 + t] = g[x * 4 + y];
        }
    }
    __syncthreads();

    {
        const int i = t >> 4, j = t & 15;
        const int l = i >> 2, L = i & 3, r = j >> 2, R = j & 3;

        // rolling C prefetch (depth 2)
        float4 cbA = *(const float4*)(Crow + t * 4);
        float4 ctA = *(const float4*)(Crow + 8192 + t * 4);
        float4 cbB = *(const float4*)(Crow + 1024 + t * 4);
        float4 ctB = *(const float4*)(Crow + 8192 + 1024 + t * 4);

#pragma unroll
        for (int x = 0; x < 8; x++) {
            float4 cbN, ctN;
            if (x < 6) {
                cbN = *(const float4*)(Crow + (x + 2) * 1024 + t * 4);
                ctN = *(const float4*)(Crow + 8192 + (x + 2) * 1024 + t * 4);
            }
            const float* sb = sm + SM_S + x * 1024;

            float r0v[4], r3v[4];
#pragma unroll
            for (int u = 0; u < 4; u++) {
                r0v[u] = sb[l * 64 + r * 16 + u];               // s0[l,r,0,u]
                r3v[u] = sb[768 + L * 64 + R * 16 + u * 4];     // s3[L,R,u,0]
            }
#pragma unroll
            for (int U = 0; U < 4; U++) {
                float a0 = 0.0f;
#pragma unroll
                for (int u = 0; u < 4; u++)
                    a0 = fmaf(r0v[u], sb[256 + L * 64 + R * 16 + u * 4 + U], a0);
                const float val = a0 + ((const float*)&cbA)[U];
                sm[SM_BOTT + x * XPL + U * PLANE + j * STR + i] = val;
                sm[SM_BOTN + x * XPL + U * PLANE + i * STR + j] = val;
            }
#pragma unroll
            for (int d = 0; d < 4; d++) {
                float a0 = 0.0f;
#pragma unroll
                for (int u = 0; u < 4; u++)
                    a0 = fmaf(sb[512 + l * 64 + r * 16 + d * 4 + u], r3v[u], a0);
                const float val = a0 + ((const float*)&ctA)[d];
                sm[SM_TOPT + x * XPL + d * PLANE + j * STR + i] = val;
                sm[SM_TOPN + x * XPL + d * PLANE + i * STR + j] = val;
            }
            cbA = cbB; ctA = ctB;
            cbB = cbN; ctB = ctN;
        }
    }

    // ---------------- Phase 2: two half-chains ----------------
    const int half = t >> 7;
    const int ht   = t & 127;
    const int I    = ht & 15;
    const int j2   = ht >> 4;                 // 0..7; owns rows j2, j2+8

    float* Vh = sm + SM_V + half * 640;
    for (int q = ht; q < 640; q += 128)
        Vh[q] = (q == 0) ? 1.0f : 0.0f;       // V[0,0]=1 in buffer 0
    __syncthreads();                          // builds + V init visible

    const float* botH = sm + (half ? SM_BOTN : SM_BOTT);
    const float* topH = sm + (half ? SM_TOPN : SM_TOPT);
    float* P4h = sm + SM_P4 + half * 1024;
    const int barid = half + 1;

    float a0 = 0.0f, a1 = 0.0f;

#pragma unroll
    for (int s4 = 0; s4 < 4; s4++) {
        const int x = half ? (7 - s4) : s4;
        const float* bx = botH + x * XPL;
        const float* tx = topH + x * XPL;
        const float* Vin  = Vh + (s4 & 1) * 320;
        float*       Vout = Vh + ((s4 + 1) & 1) * 320;

        // vl = column I of Vin (shared by both owned rows)
        float vl[16];
#pragma unroll
        for (int q = 0; q < 4; q++) {
            float4 v4 = *(const float4*)(Vin + I * STR + q * 4);
            vl[4 * q + 0] = v4.x; vl[4 * q + 1] = v4.y;
            vl[4 * q + 2] = v4.z; vl[4 * q + 3] = v4.w;
        }

        // P_u[jj, I] = sum_ii bot_u[ii, jj] * V[ii, I], jj in {j2, j2+8}
#pragma unroll
        for (int u = 0; u < 4; u++) {
            const float4* b0 = (const float4*)(bx + u * PLANE + j2 * STR);
            const float4* b1 = (const float4*)(bx + u * PLANE + (j2 + 8) * STR);
            float p0 = 0.0f, p1 = 0.0f;
#pragma unroll
            for (int q = 0; q < 4; q++) {
                float4 x0 = b0[q], x1 = b1[q];
                p0 = fmaf(x0.x, vl[4 * q + 0], p0);
                p1 = fmaf(x1.x, vl[4 * q + 0], p1);
                p0 = fmaf(x0.y, vl[4 * q + 1], p0);
                p1 = fmaf(x1.y, vl[4 * q + 1], p1);
                p0 = fmaf(x0.z, vl[4 * q + 2], p0);
                p1 = fmaf(x1.z, vl[4 * q + 2], p1);
                p0 = fmaf(x0.w, vl[4 * q + 3], p0);
                p1 = fmaf(x1.w, vl[4 * q + 3], p1);
            }
            P4h[u * 256 + j2 * 16 + I]       = p0;
            P4h[u * 256 + (j2 + 8) * 16 + I] = p1;
        }
        asm volatile("bar.sync %0, %1;" :: "r"(barid), "r"(128) : "memory");

        // V'[jj, I] = sum_u sum_I2 P_u[jj, I2] * top_u[I2, I]
        float acc0 = 0.0f, acc1 = 0.0f;
#pragma unroll
        for (int u = 0; u < 4; u++) {
            const float4* tc  = (const float4*)(tx + u * PLANE + I * STR);
            const float4* pr0 = (const float4*)(P4h + u * 256 + j2 * 16);
            const float4* pr1 = (const float4*)(P4h + u * 256 + (j2 + 8) * 16);
#pragma unroll
            for (int q = 0; q < 4; q++) {
                float4 tq = tc[q];
                float4 pa = pr0[q], pb = pr1[q];
                acc0 = fmaf(pa.x, tq.x, acc0);
                acc1 = fmaf(pb.x, tq.x, acc1);
                acc0 = fmaf(pa.y, tq.y, acc0);
                acc1 = fmaf(pb.y, tq.y, acc1);
                acc0 = fmaf(pa.z, tq.z, acc0);
                acc1 = fmaf(pb.z, tq.z, acc1);
                acc0 = fmaf(pa.w, tq.w, acc0);
                acc1 = fmaf(pb.w, tq.w, acc1);
            }
        }
        Vout[I * STR + j2]     = acc0;
        Vout[I * STR + j2 + 8] = acc1;
        a0 = acc0; a1 = acc1;
        asm volatile("bar.sync %0, %1;" :: "r"(barid), "r"(128) : "memory");
    }

    // ---------------- combine: dot of the two half-results ----------------
    float* VF = sm + SM_VF;
    VF[half * 256 + j2 * 16 + I]       = a0;
    VF[half * 256 + (j2 + 8) * 16 + I] = a1;
    __syncthreads();

    float prod = VF[t] * VF[256 + t];
#pragma unroll
    for (int o = 16; o; o >>= 1)
        prod += __shfl_xor_sync(0xffffffffu, prod, o);
    if ((t & 31) == 0) sm[SM_RED + (t >> 5)] = prod;
    __syncthreads();
    if (t < 8) {
        float v = sm[SM_RED + t];
        v += __shfl_xor_sync(0xffu, v, 4);
        v += __shfl_xor_sync(0xffu, v, 2);
        v += __shfl_xor_sync(0xffu, v, 1);
        if (t == 0) out[b] = v;
    }
}

// ---------------------------------------------------------------------------
extern "C" void kernel_launch(void* const* d_in, const int* in_sizes, int n_in,
                              void* d_out, int out_size) {
    const int*   cfg = (const int*)d_in[0];
    const float* A   = (const float*)d_in[1];
    const float* W1  = (const float*)d_in[2];
    const float* b1  = (const float*)d_in[3];
    const float* W2  = (const float*)d_in[4];
    const float* b2  = (const float*)d_in[5];
    float* out = (float*)d_out;

    cudaFuncSetAttribute(k_chain, cudaFuncAttributeMaxDynamicSharedMemorySize,
                         SMEM_CH);

    k_gemm<<<dim3(32, 4), 512>>>(cfg, W1, b1, W2, b2);
    k_chain<<<NB, 256, SMEM_CH>>>(cfg, A, out);
}

// round 7
// speedup vs baseline: 1.5342x; 1.1712x over previous
#include <cuda_runtime.h>

// Problem constants: LX=8, LY=4, D=4, PHYS=2, batch=128
#define NB   128
#define NCOL 16384

__device__ __align__(16) float g_C[NB * NCOL];

// f32x2 packed helpers (sm_100+ PTX)
#define FMA2(d, a, b) asm("fma.rn.f32x2 %0, %1, %2, %0;" : "+l"(d) : "l"(a), "l"(b))
#define PACK2(d, lo, hi) asm("mov.b64 %0, {%1, %2};" : "=l"(d) : "f"(lo), "f"(hi))
#define UNPACK2(lo, hi, s) asm("mov.b64 {%0, %1}, %2;" : "=f"(lo), "=f"(hi) : "l"(s))

// ---------------------------------------------------------------------------
// Kernel 1 (fused hidden + gemm), 512 threads, 2 cols x 16 batches / thread:
//   H[b,k] = relu(b1[k] + cfg[b,:]·W1[:,k])
//   C[b,n] = 0.001 * (b2[n] + H[b,:]·W2[:,n])
// grid (16, 8) = 128 blocks = 1 wave.
// ---------------------------------------------------------------------------
__global__ void __launch_bounds__(512, 1)
k_gemm(const int* __restrict__ cfg,
       const float* __restrict__ W1,
       const float* __restrict__ b1,
       const float* __restrict__ W2,
       const float* __restrict__ b2) {
    __shared__ __align__(16) float Hs[64 * 16];   // [hidden k][batch]
    __shared__ int cs[16 * 32];                    // [batch][cfg k]

    const int tid = threadIdx.x;
    const int n0  = blockIdx.x * 1024 + tid * 2;
    const int b0  = blockIdx.y * 16;

    if (tid < 512) cs[tid] = cfg[b0 * 32 + tid];
    __syncthreads();

    // hidden: thread owns hidden index j, batches bl and bl+8
    {
        const int j  = tid & 63;
        const int bl = tid >> 6;          // 0..7
        float w1c[32];
#pragma unroll
        for (int k = 0; k < 32; k++) w1c[k] = W1[k * 64 + j];
        const float bj = b1[j];
        float acc0 = bj, acc1 = bj;
#pragma unroll
        for (int k = 0; k < 32; k++) {
            acc0 = fmaf((float)cs[bl * 32 + k],       w1c[k], acc0);
            acc1 = fmaf((float)cs[(bl + 8) * 32 + k], w1c[k], acc1);
        }
        Hs[j * 16 + bl]     = fmaxf(acc0, 0.0f);
        Hs[j * 16 + bl + 8] = fmaxf(acc1, 0.0f);
    }
    __syncthreads();

    // GEMM: acc0 = col n0, acc1 = col n0+1; 8 batch-pairs each (f32x2)
    unsigned long long acc0[8], acc1[8];
    {
        const float2 bb = *(const float2*)(b2 + n0);
        unsigned long long z0, z1;
        PACK2(z0, bb.x, bb.x);
        PACK2(z1, bb.y, bb.y);
#pragma unroll
        for (int p = 0; p < 8; p++) { acc0[p] = z0; acc1[p] = z1; }
    }

#pragma unroll 8
    for (int k = 0; k < 64; k++) {
        const float2 w = *(const float2*)(W2 + k * NCOL + n0);
        unsigned long long w0p, w1p;
        PACK2(w0p, w.x, w.x);
        PACK2(w1p, w.y, w.y);
        const ulonglong2* hp = (const ulonglong2*)(Hs + k * 16);
#pragma unroll
        for (int q = 0; q < 4; q++) {
            ulonglong2 hh = hp[q];               // batches 4q..4q+3 (broadcast)
            FMA2(acc0[2 * q],     hh.x, w0p);
            FMA2(acc1[2 * q],     hh.x, w1p);
            FMA2(acc0[2 * q + 1], hh.y, w0p);
            FMA2(acc1[2 * q + 1], hh.y, w1p);
        }
    }

#pragma unroll
    for (int p = 0; p < 8; p++) {
        float l0, h0, l1, h1;
        UNPACK2(l0, h0, acc0[p]);
        UNPACK2(l1, h1, acc1[p]);
        *(float2*)(g_C + (b0 + 2 * p)     * NCOL + n0) = make_float2(0.001f * l0, 0.001f * l1);
        *(float2*)(g_C + (b0 + 2 * p + 1) * NCOL + n0) = make_float2(0.001f * h0, 0.001f * h1);
    }
}

// ---------------------------------------------------------------------------
// Kernel 2: per-batch assembly + SPLIT transfer-matrix chain. 512 threads.
//
// Phase 1 (512 threads): group h = t>>8 stages + builds x in [4h, 4h+4):
//   single barrier between staging and builds; dual layouts (stride 20):
//   botT[x][u][j*20+i], botN[x][u][i*20+j] (top same).
//
// Phase 2 (threads 0-255): half 0 forward chain x=0..3, half 1 adjoint chain
// x=7..4 (reads N layouts); named barriers (128 threads each).
// Final: dot of the two 256-element results.
// ---------------------------------------------------------------------------
#define STR   20
#define PLANE 320      // 16*STR
#define XPL   1280     // 4*PLANE

#define SM_S    0       // 8192
#define SM_BOTT 8192    // 10240
#define SM_TOPT 18432   // 10240
#define SM_BOTN 28672   // 10240
#define SM_TOPN 38912   // 10240
#define SM_P4   49152   // 2*1024
#define SM_V    51200   // 2*640
#define SM_VF   52480   // 512
#define SM_RED  52992   // 16
#define SM_CFG  53008   // 32 ints
#define SMEM_CH (53040 * 4)

__global__ void __launch_bounds__(512, 1)
k_chain(const int* __restrict__ cfg,
        const float* __restrict__ A,
        float* __restrict__ out) {
    extern __shared__ __align__(16) float sm[];
    int* c = (int*)(sm + SM_CFG);

    const int b = blockIdx.x;
    const int t = threadIdx.x;

    if (t < 32) c[t] = cfg[b * 32 + t];
    __syncthreads();

    const float* Crow = g_C + b * NCOL;
    const int p = t & 255;
    const int h = t >> 8;            // x-group: h=0 -> x 0..3, h=1 -> x 4..7

    // ---------------- Phase 1: stage s (this group's 4 x), build ----------------
    {
        float g[16];
#pragma unroll
        for (int q = 0; q < 16; q++) {
            const int x = h * 4 + (q >> 2), y = q & 3;
            g[q] = A[x * 2048 + y * 512 + p * 2 + c[x * 4 + y]];
        }
#pragma unroll
        for (int q = 0; q < 16; q++) {
            const int x = h * 4 + (q >> 2), y = q & 3;
            sm[SM_S + x * 1024 + y * 256 + p] = g[q];
        }
    }
    __syncthreads();

    {
        const int i = p >> 4, j = p & 15;
        const int l = i >> 2, L = i & 3, r = j >> 2, R = j & 3;

        // prefetch all 4 x-sites' C corrections (MLP-8)
        float4 cb[4], ct[4];
#pragma unroll
        for (int q = 0; q < 4; q++) {
            const int x = h * 4 + q;
            cb[q] = *(const float4*)(Crow + x * 1024 + p * 4);
            ct[q] = *(const float4*)(Crow + 8192 + x * 1024 + p * 4);
        }

#pragma unroll
        for (int q = 0; q < 4; q++) {
            const int x = h * 4 + q;
            const float* sb = sm + SM_S + x * 1024;

            float r0v[4], r3v[4];
#pragma unroll
            for (int u = 0; u < 4; u++) {
                r0v[u] = sb[l * 64 + r * 16 + u];               // s0[l,r,0,u]
                r3v[u] = sb[768 + L * 64 + R * 16 + u * 4];     // s3[L,R,u,0]
            }
#pragma unroll
            for (int U = 0; U < 4; U++) {
                float a0 = 0.0f;
#pragma unroll
                for (int u = 0; u < 4; u++)
                    a0 = fmaf(r0v[u], sb[256 + L * 64 + R * 16 + u * 4 + U], a0);
                const float val = a0 + ((const float*)&cb[q])[U];
                sm[SM_BOTT + x * XPL + U * PLANE + j * STR + i] = val;
                sm[SM_BOTN + x * XPL + U * PLANE + i * STR + j] = val;
            }
#pragma unroll
            for (int d = 0; d < 4; d++) {
                float a0 = 0.0f;
#pragma unroll
                for (int u = 0; u < 4; u++)
                    a0 = fmaf(sb[512 + l * 64 + r * 16 + d * 4 + u], r3v[u], a0);
                const float val = a0 + ((const float*)&ct[q])[d];
                sm[SM_TOPT + x * XPL + d * PLANE + j * STR + i] = val;
                sm[SM_TOPN + x * XPL + d * PLANE + i * STR + j] = val;
            }
        }
    }
    __syncthreads();   // all bot/top visible to phase 2

    // ---------------- Phase 2: two half-chains (threads 0-255) ----------------
    if (t < 256) {
        const int half = t >> 7;
        const int ht   = t & 127;
        const int I    = ht & 15;
        const int j2   = ht >> 4;             // owns rows j2, j2+8

        float* Vh = sm + SM_V + half * 640;
        for (int q = ht; q < 640; q += 128)
            Vh[q] = (q == 0) ? 1.0f : 0.0f;   // V[0,0]=1 in buffer 0

        const float* botH = sm + (half ? SM_BOTN : SM_BOTT);
        const float* topH = sm + (half ? SM_TOPN : SM_TOPT);
        float* P4h = sm + SM_P4 + half * 1024;
        const int barid = half + 1;
        asm volatile("bar.sync %0, %1;" :: "r"(barid), "r"(128) : "memory");

        float a0 = 0.0f, a1 = 0.0f;

#pragma unroll
        for (int s4 = 0; s4 < 4; s4++) {
            const int x = half ? (7 - s4) : s4;
            const float* bx = botH + x * XPL;
            const float* tx = topH + x * XPL;
            const float* Vin  = Vh + (s4 & 1) * 320;
            float*       Vout = Vh + ((s4 + 1) & 1) * 320;

            float vl[16];
#pragma unroll
            for (int q = 0; q < 4; q++) {
                float4 v4 = *(const float4*)(Vin + I * STR + q * 4);
                vl[4 * q + 0] = v4.x; vl[4 * q + 1] = v4.y;
                vl[4 * q + 2] = v4.z; vl[4 * q + 3] = v4.w;
            }

#pragma unroll
            for (int u = 0; u < 4; u++) {
                const float4* bp0 = (const float4*)(bx + u * PLANE + j2 * STR);
                const float4* bp1 = (const float4*)(bx + u * PLANE + (j2 + 8) * STR);
                float p0 = 0.0f, p1 = 0.0f;
#pragma unroll
                for (int q = 0; q < 4; q++) {
                    float4 x0 = bp0[q], x1 = bp1[q];
                    p0 = fmaf(x0.x, vl[4 * q + 0], p0);
                    p1 = fmaf(x1.x, vl[4 * q + 0], p1);
                    p0 = fmaf(x0.y, vl[4 * q + 1], p0);
                    p1 = fmaf(x1.y, vl[4 * q + 1], p1);
                    p0 = fmaf(x0.z, vl[4 * q + 2], p0);
                    p1 = fmaf(x1.z, vl[4 * q + 2], p1);
                    p0 = fmaf(x0.w, vl[4 * q + 3], p0);
                    p1 = fmaf(x1.w, vl[4 * q + 3], p1);
                }
                P4h[u * 256 + j2 * 16 + I]       = p0;
                P4h[u * 256 + (j2 + 8) * 16 + I] = p1;
            }
            asm volatile("bar.sync %0, %1;" :: "r"(barid), "r"(128) : "memory");

            float acc0 = 0.0f, acc1 = 0.0f;
#pragma unroll
            for (int u = 0; u < 4; u++) {
                const float4* tc  = (const float4*)(tx + u * PLANE + I * STR);
                const float4* pr0 = (const float4*)(P4h + u * 256 + j2 * 16);
                const float4* pr1 = (const float4*)(P4h + u * 256 + (j2 + 8) * 16);
#pragma unroll
                for (int q = 0; q < 4; q++) {
                    float4 tq = tc[q];
                    float4 pa = pr0[q], pb = pr1[q];
                    acc0 = fmaf(pa.x, tq.x, acc0);
                    acc1 = fmaf(pb.x, tq.x, acc1);
                    acc0 = fmaf(pa.y, tq.y, acc0);
                    acc1 = fmaf(pb.y, tq.y, acc1);
                    acc0 = fmaf(pa.z, tq.z, acc0);
                    acc1 = fmaf(pb.z, tq.z, acc1);
                    acc0 = fmaf(pa.w, tq.w, acc0);
                    acc1 = fmaf(pb.w, tq.w, acc1);
                }
            }
            Vout[I * STR + j2]     = acc0;
            Vout[I * STR + j2 + 8] = acc1;
            a0 = acc0; a1 = acc1;
            asm volatile("bar.sync %0, %1;" :: "r"(barid), "r"(128) : "memory");
        }

        float* VF = sm + SM_VF;
        VF[half * 256 + j2 * 16 + I]       = a0;
        VF[half * 256 + (j2 + 8) * 16 + I] = a1;
    }
    __syncthreads();

    // ---------------- combine: dot of the two half-results ----------------
    if (t < 256) {
        const float* VF = sm + SM_VF;
        float prod = VF[t] * VF[256 + t];
#pragma unroll
        for (int o = 16; o; o >>= 1)
            prod += __shfl_xor_sync(0xffffffffu, prod, o);
        if ((t & 31) == 0) sm[SM_RED + (t >> 5)] = prod;
    }
    __syncthreads();
    if (t < 8) {
        float v = sm[SM_RED + t];
        v += __shfl_xor_sync(0xffu, v, 4);
        v += __shfl_xor_sync(0xffu, v, 2);
        v += __shfl_xor_sync(0xffu, v, 1);
        if (t == 0) out[b] = v;
    }
}

// ---------------------------------------------------------------------------
extern "C" void kernel_launch(void* const* d_in, const int* in_sizes, int n_in,
                              void* d_out, int out_size) {
    const int*   cfg = (const int*)d_in[0];
    const float* A   = (const float*)d_in[1];
    const float* W1  = (const float*)d_in[2];
    const float* b1  = (const float*)d_in[3];
    const float* W2  = (const float*)d_in[4];
    const float* b2  = (const float*)d_in[5];
    float* out = (float*)d_out;

    cudaFuncSetAttribute(k_chain, cudaFuncAttributeMaxDynamicSharedMemorySize,
                         SMEM_CH);

    k_gemm<<<dim3(16, 8), 512>>>(cfg, W1, b1, W2, b2);
    k_chain<<<NB, 512, SMEM_CH>>>(cfg, A, out);
}